// round 8
// baseline (speedup 1.0000x reference)
#include <cuda_runtime.h>
#include <math.h>
#include <stdint.h>

// ---------------------------------------------------------------------------
// out[k] = sigmoid( concat(feature[a], feature[b]) @ W1 @ W2 @ W3 @ W4 + c )
// Collapsed affine form (no inter-layer activations):
//   v4 = W4[:,0] (64), v3 = W3 v4 (512), v2 = W2 v3 (1024), v1 = W1 v2 (1802)
//   c  = b1.v2 + b2.v3 + b3.v4 + b4[0]
//   s1[e] = feature[e] . v1[0:901], s2[e] = feature[e] . v1[901:1802]
//   out[k] = sigmoid(s1[a] + s2[b] + c)
//
// k_scores_out: streams feature (72 MB) via cp.async.bulk into a 3-stage smem
// ring; 8 consumer warps dot-product one row each with v1 in registers.
// Pair indices preloaded into registers BEFORE the stream (hides the 1 MB idx
// read), then an epoch grid barrier, then in-kernel gather+sigmoid epilogue.
// ---------------------------------------------------------------------------

#define N_ENT 20000
#define D     901
#define B_TR  100000
#define B_TE  25000
#define N_PAIR (B_TR + B_TE)

#define TILE_ROWS  8
#define TILE_BYTES (TILE_ROWS * D * 4)     // 28832, multiple of 16
#define N_TILES    (N_ENT / TILE_ROWS)     // 2500
#define SC_GRID    296
#define SC_THREADS 288                     // 8 consumer warps + 1 producer warp
#define SC_SMEM    (64 + 3 * TILE_BYTES)   // 86560 bytes
#define N_THREADS_TOT (SC_GRID * SC_THREADS)   // 85248

__device__ __align__(16) float g_v3[512];
__device__ __align__(16) float g_v2[1024];
__device__ __align__(16) float g_v1[2 * D];    // collapsed weight vector
__device__ float g_c;
__device__ __align__(16) float g_s[2 * N_ENT]; // s1[e]=g_s[2e], s2[e]=g_s[2e+1]
__device__ unsigned long long g_bar;           // epoch grid barrier (never reset)

// ---- mbarrier / bulk-copy primitives ----
__device__ __forceinline__ void mbar_init(uint32_t addr, uint32_t count) {
    asm volatile("mbarrier.init.shared.b64 [%0], %1;" :: "r"(addr), "r"(count) : "memory");
}
__device__ __forceinline__ void mbar_expect_tx(uint32_t addr, uint32_t bytes) {
    asm volatile("mbarrier.arrive.expect_tx.shared.b64 _, [%0], %1;"
                 :: "r"(addr), "r"(bytes) : "memory");
}
__device__ __forceinline__ void mbar_arrive(uint32_t addr) {
    asm volatile("mbarrier.arrive.shared.b64 _, [%0];" :: "r"(addr) : "memory");
}
__device__ __forceinline__ void mbar_wait(uint32_t addr, uint32_t parity) {
    asm volatile(
        "{\n\t.reg .pred P;\n\t"
        "WAIT_%=:\n\t"
        "mbarrier.try_wait.parity.acquire.cta.shared::cta.b64 P, [%0], %1, 0x989680;\n\t"
        "@P bra.uni DONE_%=;\n\t"
        "bra.uni WAIT_%=;\n\t"
        "DONE_%=:\n\t}"
        :: "r"(addr), "r"(parity) : "memory");
}
__device__ __forceinline__ void bulk_g2s(uint32_t dst_smem, const void* src_gmem,
                                         uint32_t bytes, uint32_t mbar) {
    asm volatile(
        "cp.async.bulk.shared::cluster.global.mbarrier::complete_tx::bytes [%0], [%1], %2, [%3];"
        :: "r"(dst_smem), "l"(src_gmem), "r"(bytes), "r"(mbar) : "memory");
}

// ---- fused: v3 = W3 @ W4col (coalesced warp-per-row, per-block redundant),
//      then v2 = W2 @ v3 ----
__global__ void __launch_bounds__(256) k_v23(const float* __restrict__ W3,
                                             const float* __restrict__ W4,
                                             const float* __restrict__ W2) {
    __shared__ float s_v3[512];
    __shared__ float s_w4[64];
    int t = threadIdx.x;
    int warp = t >> 5, lane = t & 31;
    if (t < 64) s_w4[t] = __ldg(W4 + t);
    __syncthreads();
    float w4a = s_w4[lane], w4b = s_w4[lane + 32];
    for (int r = warp; r < 512; r += 8) {
        const float* row = W3 + r * 64;
        float a = fmaf(__ldg(row + lane), w4a, __ldg(row + lane + 32) * w4b);
        #pragma unroll
        for (int o = 16; o; o >>= 1) a += __shfl_down_sync(0xffffffffu, a, o);
        if (lane == 0) s_v3[r] = a;
    }
    __syncthreads();

    int r = blockIdx.x * 8 + warp;                 // 128 blocks * 8 warps = 1024 rows
    const float4* row = (const float4*)W2 + (size_t)r * 128;
    const float4* v   = (const float4*)s_v3;
    float acc = 0.f;
    #pragma unroll
    for (int i = 0; i < 4; i++) {
        int j = lane + 32 * i;
        float4 a4 = __ldg(row + j);
        float4 b4 = v[j];
        acc = fmaf(a4.x, b4.x, acc);
        acc = fmaf(a4.y, b4.y, acc);
        acc = fmaf(a4.z, b4.z, acc);
        acc = fmaf(a4.w, b4.w, acc);
    }
    #pragma unroll
    for (int o = 16; o; o >>= 1) acc += __shfl_down_sync(0xffffffffu, acc, o);
    if (lane == 0) g_v2[r] = acc;

    if (blockIdx.x == 0) {                          // publish v3 for the bias kernel
        __syncthreads();
        for (int rr = t; rr < 512; rr += 256) g_v3[rr] = s_v3[rr];
    }
}

// ---- v1 = W1 @ v2 (1802 warp-rows). Last block computes the bias constant. ----
__global__ void __launch_bounds__(256) k_v1_bias(const float* __restrict__ W1,
                          const float* __restrict__ b1, const float* __restrict__ b2,
                          const float* __restrict__ b3, const float* __restrict__ b4,
                          const float* __restrict__ W4) {
    if (blockIdx.x == gridDim.x - 1) {
        __shared__ float red[8];
        int t = threadIdx.x;
        float acc = 0.f;
        #pragma unroll
        for (int j = t; j < 1024; j += 256) acc = fmaf(__ldg(b1 + j), g_v2[j], acc);
        #pragma unroll
        for (int j = t; j < 512; j += 256)  acc = fmaf(__ldg(b2 + j), g_v3[j], acc);
        if (t < 64)                         acc = fmaf(__ldg(b3 + t), __ldg(W4 + t), acc);
        #pragma unroll
        for (int o = 16; o; o >>= 1) acc += __shfl_down_sync(0xffffffffu, acc, o);
        if ((t & 31) == 0) red[t >> 5] = acc;
        __syncthreads();
        if (t == 0) {
            float s = __ldg(b4);
            #pragma unroll
            for (int w = 0; w < 8; w++) s += red[w];
            g_c = s;
        }
        return;
    }
    int warp = (blockIdx.x * blockDim.x + threadIdx.x) >> 5;
    int lane = threadIdx.x & 31;
    if (warp >= 2 * D) return;
    const float4* row = (const float4*)W1 + (size_t)warp * 256;  // 1024/4
    const float4* v4  = (const float4*)g_v2;
    float acc = 0.f;
    #pragma unroll
    for (int i = 0; i < 8; i++) {
        int j = lane + 32 * i;
        float4 a = __ldg(row + j);
        float4 b = v4[j];
        acc = fmaf(a.x, b.x, acc);
        acc = fmaf(a.y, b.y, acc);
        acc = fmaf(a.z, b.z, acc);
        acc = fmaf(a.w, b.w, acc);
    }
    #pragma unroll
    for (int o = 16; o; o >>= 1) acc += __shfl_down_sync(0xffffffffu, acc, o);
    if (lane == 0) g_v1[warp] = acc;
}

// ---- scores (bulk-copy pipeline) + grid barrier + gather/sigmoid epilogue ----
__global__ void __launch_bounds__(SC_THREADS) k_scores_out(
        const float* __restrict__ feat,
        const int2* __restrict__ tr, const int2* __restrict__ te,
        float* __restrict__ out) {
    extern __shared__ __align__(16) unsigned char smem_raw[];
    uint32_t smem = (uint32_t)__cvta_generic_to_shared(smem_raw);
    float* smemf = (float*)smem_raw;
    const uint32_t mb_full    = smem;        // 3 x 8B at 0,8,16
    const uint32_t mb_empty   = smem + 24;   // 3 x 8B at 24,32,40
    const uint32_t stage_base = smem + 64;

    int tid = threadIdx.x;
    int b   = blockIdx.x;

    // ---- preload pair indices (independent of scores; hides 1MB idx DRAM read)
    int gt = b * SC_THREADS + tid;
    int k0 = gt, k1 = gt + N_THREADS_TOT;
    int2 p0 = make_int2(0, 0), p1 = make_int2(0, 0);
    if (k0 < N_PAIR) p0 = (k0 < B_TR) ? __ldg(tr + k0) : __ldg(te + (k0 - B_TR));
    if (k1 < N_PAIR) p1 = (k1 < B_TR) ? __ldg(tr + k1) : __ldg(te + (k1 - B_TR));

    if (tid == 0) {
        #pragma unroll
        for (int s = 0; s < 3; s++) {
            mbar_init(mb_full  + 8u * s, 1);
            mbar_init(mb_empty + 8u * s, 8);
        }
    }
    __syncthreads();

    if (tid >= 256) {
        // ---- producer warp (single thread issues bulk copies) ----
        if (tid == 256) {
            int it = 0;
            for (int t = b; t < N_TILES; t += SC_GRID, it++) {
                int s  = it % 3;
                int ph = ((it / 3) & 1) ^ 1;   // first use of each stage passes
                mbar_wait(mb_empty + 8u * s, ph);
                mbar_expect_tx(mb_full + 8u * s, TILE_BYTES);
                bulk_g2s(stage_base + (uint32_t)s * TILE_BYTES,
                         feat + (size_t)t * TILE_ROWS * D,
                         TILE_BYTES, mb_full + 8u * s);
            }
        }
    } else {
        // ---- consumer warps: one row per warp per tile, weights in registers ----
        int warp = tid >> 5, lane = tid & 31;
        float rw1[28], rw2[28];
        #pragma unroll
        for (int i = 0; i < 28; i++) {
            rw1[i] = __ldg(g_v1 + lane + 32 * i);
            rw2[i] = __ldg(g_v1 + D + lane + 32 * i);
        }
        float rw1t = 0.f, rw2t = 0.f;
        if (lane < 5) {
            rw1t = __ldg(g_v1 + 896 + lane);
            rw2t = __ldg(g_v1 + D + 896 + lane);
        }

        int it = 0;
        for (int t = b; t < N_TILES; t += SC_GRID, it++) {
            int s  = it % 3;
            int ph = (it / 3) & 1;
            mbar_wait(mb_full + 8u * s, ph);
            int rbase = 16 + s * (TILE_BYTES / 4) + warp * D;   // float idx of row
            float s1 = 0.f, s2 = 0.f;
            #pragma unroll
            for (int i = 0; i < 28; i++) {
                float f = smemf[rbase + lane + 32 * i];
                s1 = fmaf(f, rw1[i], s1);
                s2 = fmaf(f, rw2[i], s2);
            }
            if (lane < 5) {
                float f = smemf[rbase + 896 + lane];
                s1 = fmaf(f, rw1t, s1);
                s2 = fmaf(f, rw2t, s2);
            }
            #pragma unroll
            for (int o = 16; o; o >>= 1) {
                s1 += __shfl_down_sync(0xffffffffu, s1, o);
                s2 += __shfl_down_sync(0xffffffffu, s2, o);
            }
            if (lane == 0) {
                int row = t * TILE_ROWS + warp;
                g_s[2 * row]     = s1;
                g_s[2 * row + 1] = s2;
                mbar_arrive(mb_empty + 8u * s);   // after reduce: lanes done reading
            }
        }
    }

    // ---- epoch grid barrier: all g_s writes visible before any gather ----
    __syncthreads();
    __threadfence();
    __shared__ unsigned long long s_target;
    if (tid == 0) {
        unsigned long long ticket = atomicAdd(&g_bar, 1ULL);
        unsigned long long target = (ticket / SC_GRID + 1ULL) * SC_GRID;
        while (*(volatile unsigned long long*)&g_bar < target) { }
        s_target = target;   // dummy use; also publishes release of spin
    }
    __syncthreads();
    __threadfence();

    // ---- gather + sigmoid epilogue (pairs already in registers) ----
    float c = g_c;
    if (k0 < N_PAIR) {
        float z = g_s[2 * p0.x] + g_s[2 * p0.y + 1] + c;
        out[k0] = 1.0f / (1.0f + __expf(-z));
    }
    if (k1 < N_PAIR) {
        float z = g_s[2 * p1.x] + g_s[2 * p1.y + 1] + c;
        out[k1] = 1.0f / (1.0f + __expf(-z));
    }
}

extern "C" void kernel_launch(void* const* d_in, const int* in_sizes, int n_in,
                              void* d_out, int out_size) {
    const float* feature = (const float*)d_in[0];   // [20000, 901]
    const float* W1      = (const float*)d_in[1];   // [1802, 1024]
    const float* b1      = (const float*)d_in[2];   // [1024]
    const float* W2      = (const float*)d_in[3];   // [1024, 512]
    const float* b2      = (const float*)d_in[4];   // [512]
    const float* W3      = (const float*)d_in[5];   // [512, 64]
    const float* b3      = (const float*)d_in[6];   // [64]
    const float* W4      = (const float*)d_in[7];   // [64, 1]
    const float* b4      = (const float*)d_in[8];   // [1]
    const int2*  tr      = (const int2*)d_in[9];    // [100000, 2]
    const int2*  te      = (const int2*)d_in[10];   // [25000, 2]
    float*       out     = (float*)d_out;

    cudaFuncSetAttribute(k_scores_out, cudaFuncAttributeMaxDynamicSharedMemorySize, SC_SMEM);

    // v3 + v2 (fused), 128 blocks x 8 warps = 1024 rows
    k_v23<<<128, 256>>>(W3, W4, W2);
    // v1 (1802 rows) + bias constant (last block)
    k_v1_bias<<<(2 * D + 7) / 8 + 1, 256>>>(W1, b1, b2, b3, b4, W4);
    // scores + grid barrier + gather/sigmoid, all in one launch
    k_scores_out<<<SC_GRID, SC_THREADS, SC_SMEM>>>(feature, tr, te, out);
}

// round 9
// speedup vs baseline: 1.2092x; 1.2092x over previous
#include <cuda_runtime.h>
#include <math.h>
#include <stdint.h>

// ---------------------------------------------------------------------------
// out[k] = sigmoid( concat(feature[a], feature[b]) @ W1 @ W2 @ W3 @ W4 + c )
// Collapsed affine form (no inter-layer activations):
//   v4 = W4[:,0] (64), v3 = W3 v4 (512), v2 = W2 v3 (1024), v1 = W1 v2 (1802)
//   c  = b1.v2 + b2.v3 + b3.v4 + b4[0]
//   s1[e] = feature[e] . v1[0:901], s2[e] = feature[e] . v1[901:1802]
//   out[k] = sigmoid(s1[a] + s2[b] + c)
//
// SINGLE mega-kernel: producer warp streams feature (72 MB) via cp.async.bulk
// into a 3-stage smem ring starting at t=0; consumer warps first compute the
// weight-collapse chain (v3 -> v2 -> v1,c) with consumer-only grid barriers
// between phases (the 25.6 MB aggregate ring hides the chain under prefetch),
// then dot-product rows from smem with v1 in registers, then a final barrier
// and the in-kernel gather+sigmoid epilogue.
// ---------------------------------------------------------------------------

#define N_ENT 20000
#define D     901
#define B_TR  100000
#define B_TE  25000
#define N_PAIR (B_TR + B_TE)

#define TILE_ROWS  8
#define TILE_BYTES (TILE_ROWS * D * 4)     // 28832, multiple of 16
#define N_TILES    (N_ENT / TILE_ROWS)     // 2500
#define SC_GRID    296                     // 2 blocks per SM, all co-resident
#define SC_THREADS 288                     // 8 consumer warps + 1 producer warp
#define N_CONS     (SC_GRID * 256)         // 75776 consumer threads
#define SC_SMEM    (64 + 3 * TILE_BYTES)   // 86560 bytes

__device__ __align__(16) float g_v3[512];
__device__ __align__(16) float g_v2[1024];
__device__ __align__(16) float g_v1[2 * D];    // collapsed weight vector
__device__ float g_c;
__device__ __align__(16) float g_s[2 * N_ENT]; // s1[e]=g_s[2e], s2[e]=g_s[2e+1]
__device__ unsigned long long g_bar;           // epoch grid barrier (never reset)

// ---- mbarrier / bulk-copy primitives ----
__device__ __forceinline__ void mbar_init(uint32_t addr, uint32_t count) {
    asm volatile("mbarrier.init.shared.b64 [%0], %1;" :: "r"(addr), "r"(count) : "memory");
}
__device__ __forceinline__ void mbar_expect_tx(uint32_t addr, uint32_t bytes) {
    asm volatile("mbarrier.arrive.expect_tx.shared.b64 _, [%0], %1;"
                 :: "r"(addr), "r"(bytes) : "memory");
}
__device__ __forceinline__ void mbar_arrive(uint32_t addr) {
    asm volatile("mbarrier.arrive.shared.b64 _, [%0];" :: "r"(addr) : "memory");
}
__device__ __forceinline__ void mbar_wait(uint32_t addr, uint32_t parity) {
    asm volatile(
        "{\n\t.reg .pred P;\n\t"
        "WAIT_%=:\n\t"
        "mbarrier.try_wait.parity.acquire.cta.shared::cta.b64 P, [%0], %1, 0x989680;\n\t"
        "@P bra.uni DONE_%=;\n\t"
        "bra.uni WAIT_%=;\n\t"
        "DONE_%=:\n\t}"
        :: "r"(addr), "r"(parity) : "memory");
}
__device__ __forceinline__ void bulk_g2s(uint32_t dst_smem, const void* src_gmem,
                                         uint32_t bytes, uint32_t mbar) {
    asm volatile(
        "cp.async.bulk.shared::cluster.global.mbarrier::complete_tx::bytes [%0], [%1], %2, [%3];"
        :: "r"(dst_smem), "l"(src_gmem), "r"(bytes), "r"(mbar) : "memory");
}
// consumer-only (256 threads) block sync, named barrier 1
__device__ __forceinline__ void cons_sync() {
    asm volatile("bar.sync 1, 256;" ::: "memory");
}
// consumer-only grid barrier: epoch-counter, one arrival per block
__device__ __forceinline__ void cons_grid_barrier() {
    __threadfence();            // release: this thread's global writes visible
    cons_sync();                // all consumers of this block arrived
    if (threadIdx.x == 0) {
        unsigned long long ticket = atomicAdd(&g_bar, 1ULL);
        unsigned long long target = (ticket / SC_GRID + 1ULL) * SC_GRID;
        while (*(volatile unsigned long long*)&g_bar < target) { }
    }
    cons_sync();
    __threadfence();            // acquire
}

__global__ void __launch_bounds__(SC_THREADS, 2) k_all(
        const float* __restrict__ feat,
        const float* __restrict__ W1, const float* __restrict__ b1,
        const float* __restrict__ W2, const float* __restrict__ b2,
        const float* __restrict__ W3, const float* __restrict__ b3,
        const float* __restrict__ W4, const float* __restrict__ b4,
        const int2* __restrict__ tr, const int2* __restrict__ te,
        float* __restrict__ out) {
    extern __shared__ __align__(16) unsigned char smem_raw[];
    uint32_t smem = (uint32_t)__cvta_generic_to_shared(smem_raw);
    float* smemf = (float*)smem_raw;
    const uint32_t mb_full    = smem;        // 3 x 8B at 0,8,16
    const uint32_t mb_empty   = smem + 24;   // 3 x 8B at 24,32,40
    const uint32_t stage_base = smem + 64;

    int tid = threadIdx.x;
    int b   = blockIdx.x;

    if (tid == 0) {
        #pragma unroll
        for (int s = 0; s < 3; s++) {
            mbar_init(mb_full  + 8u * s, 1);
            mbar_init(mb_empty + 8u * s, 8);
        }
    }
    __syncthreads();   // all 288: mbarriers visible before producer issues

    if (tid >= 256) {
        // ---- producer warp: stream feature immediately (independent of chain)
        if (tid == 256) {
            int it = 0;
            for (int t = b; t < N_TILES; t += SC_GRID, it++) {
                int s  = it % 3;
                int ph = ((it / 3) & 1) ^ 1;   // first use of each stage passes
                mbar_wait(mb_empty + 8u * s, ph);
                mbar_expect_tx(mb_full + 8u * s, TILE_BYTES);
                bulk_g2s(stage_base + (uint32_t)s * TILE_BYTES,
                         feat + (size_t)t * TILE_ROWS * D,
                         TILE_BYTES, mb_full + 8u * s);
            }
        }
        return;   // producer never touches consumer barriers
    }

    // ================= consumer threads (256 per block) =================
    int warp = tid >> 5, lane = tid & 31;
    int cw   = b * 8 + warp;                 // global consumer warp id (0..2367)

    // pair indices preloaded up front (independent; hides 1 MB idx DRAM read)
    int k0 = b * 256 + tid, k1 = k0 + N_CONS;
    int2 p0 = make_int2(0, 0), p1 = make_int2(0, 0);
    if (k0 < N_PAIR) p0 = (k0 < B_TR) ? __ldg(tr + k0) : __ldg(te + (k0 - B_TR));
    if (k1 < N_PAIR) p1 = (k1 < B_TR) ? __ldg(tr + k1) : __ldg(te + (k1 - B_TR));

    // ---- phase 1: v3 = W3 @ W4col, one row per warp (512 warps) ----
    if (cw < 512) {
        float w4a = __ldg(W4 + lane), w4b = __ldg(W4 + 32 + lane);
        const float* row = W3 + cw * 64;
        float a = fmaf(__ldg(row + lane), w4a, __ldg(row + lane + 32) * w4b);
        #pragma unroll
        for (int o = 16; o; o >>= 1) a += __shfl_down_sync(0xffffffffu, a, o);
        if (lane == 0) g_v3[cw] = a;
    }
    cons_grid_barrier();

    // ---- phase 2: v2 = W2 @ v3, one row per warp (1024 warps) ----
    if (cw < 1024) {
        const float4* row = (const float4*)W2 + (size_t)cw * 128;
        const float4* v   = (const float4*)g_v3;
        float acc = 0.f;
        #pragma unroll
        for (int i = 0; i < 4; i++) {
            int j = lane + 32 * i;
            float4 a4 = __ldg(row + j);
            float4 b4 = __ldg(v + j);
            acc = fmaf(a4.x, b4.x, acc);
            acc = fmaf(a4.y, b4.y, acc);
            acc = fmaf(a4.z, b4.z, acc);
            acc = fmaf(a4.w, b4.w, acc);
        }
        #pragma unroll
        for (int o = 16; o; o >>= 1) acc += __shfl_down_sync(0xffffffffu, acc, o);
        if (lane == 0) g_v2[cw] = acc;
    }
    cons_grid_barrier();

    // ---- phase 3: v1 = W1 @ v2 (1802 warps); block 0 also computes c ----
    if (cw < 2 * D) {
        const float4* row = (const float4*)W1 + (size_t)cw * 256;
        const float4* v   = (const float4*)g_v2;
        float acc = 0.f;
        #pragma unroll
        for (int i = 0; i < 8; i++) {
            int j = lane + 32 * i;
            float4 a4 = __ldg(row + j);
            float4 b4 = __ldg(v + j);
            acc = fmaf(a4.x, b4.x, acc);
            acc = fmaf(a4.y, b4.y, acc);
            acc = fmaf(a4.z, b4.z, acc);
            acc = fmaf(a4.w, b4.w, acc);
        }
        #pragma unroll
        for (int o = 16; o; o >>= 1) acc += __shfl_down_sync(0xffffffffu, acc, o);
        if (lane == 0) g_v1[cw] = acc;
    }
    if (b == 0) {
        __shared__ float red[8];
        float acc = 0.f;
        #pragma unroll
        for (int j = tid; j < 1024; j += 256) acc = fmaf(__ldg(b1 + j), g_v2[j], acc);
        #pragma unroll
        for (int j = tid; j < 512; j += 256)  acc = fmaf(__ldg(b2 + j), g_v3[j], acc);
        if (tid < 64)                         acc = fmaf(__ldg(b3 + tid), __ldg(W4 + tid), acc);
        #pragma unroll
        for (int o = 16; o; o >>= 1) acc += __shfl_down_sync(0xffffffffu, acc, o);
        if (lane == 0) red[warp] = acc;
        cons_sync();
        if (tid == 0) {
            float s = __ldg(b4);
            #pragma unroll
            for (int w = 0; w < 8; w++) s += red[w];
            g_c = s;
        }
    }
    cons_grid_barrier();

    // ---- weights into registers (first touch of g_v1 on this SM: L2-fresh) ----
    float rw1[28], rw2[28];
    #pragma unroll
    for (int i = 0; i < 28; i++) {
        rw1[i] = __ldg(g_v1 + lane + 32 * i);
        rw2[i] = __ldg(g_v1 + D + lane + 32 * i);
    }
    float rw1t = 0.f, rw2t = 0.f;
    if (lane < 5) {
        rw1t = __ldg(g_v1 + 896 + lane);
        rw2t = __ldg(g_v1 + D + 896 + lane);
    }

    // ---- scores: one row per warp per tile from the smem ring ----
    int it = 0;
    for (int t = b; t < N_TILES; t += SC_GRID, it++) {
        int s  = it % 3;
        int ph = (it / 3) & 1;
        mbar_wait(mb_full + 8u * s, ph);
        int rbase = 16 + s * (TILE_BYTES / 4) + warp * D;   // float idx of row
        float s1 = 0.f, s2 = 0.f;
        #pragma unroll
        for (int i = 0; i < 28; i++) {
            float f = smemf[rbase + lane + 32 * i];
            s1 = fmaf(f, rw1[i], s1);
            s2 = fmaf(f, rw2[i], s2);
        }
        if (lane < 5) {
            float f = smemf[rbase + 896 + lane];
            s1 = fmaf(f, rw1t, s1);
            s2 = fmaf(f, rw2t, s2);
        }
        #pragma unroll
        for (int o = 16; o; o >>= 1) {
            s1 += __shfl_down_sync(0xffffffffu, s1, o);
            s2 += __shfl_down_sync(0xffffffffu, s2, o);
        }
        if (lane == 0) {
            int row = t * TILE_ROWS + warp;
            g_s[2 * row]     = s1;
            g_s[2 * row + 1] = s2;
            mbar_arrive(mb_empty + 8u * s);   // after reduce: lanes done reading
        }
    }
    cons_grid_barrier();   // all g_s visible

    // ---- gather + sigmoid epilogue (pairs already in registers) ----
    float c = g_c;
    if (k0 < N_PAIR) {
        float z = g_s[2 * p0.x] + g_s[2 * p0.y + 1] + c;
        out[k0] = 1.0f / (1.0f + __expf(-z));
    }
    if (k1 < N_PAIR) {
        float z = g_s[2 * p1.x] + g_s[2 * p1.y + 1] + c;
        out[k1] = 1.0f / (1.0f + __expf(-z));
    }
}

extern "C" void kernel_launch(void* const* d_in, const int* in_sizes, int n_in,
                              void* d_out, int out_size) {
    const float* feature = (const float*)d_in[0];   // [20000, 901]
    const float* W1      = (const float*)d_in[1];   // [1802, 1024]
    const float* b1      = (const float*)d_in[2];   // [1024]
    const float* W2      = (const float*)d_in[3];   // [1024, 512]
    const float* b2      = (const float*)d_in[4];   // [512]
    const float* W3      = (const float*)d_in[5];   // [512, 64]
    const float* b3      = (const float*)d_in[6];   // [64]
    const float* W4      = (const float*)d_in[7];   // [64, 1]
    const float* b4      = (const float*)d_in[8];   // [1]
    const int2*  tr      = (const int2*)d_in[9];    // [100000, 2]
    const int2*  te      = (const int2*)d_in[10];   // [25000, 2]
    float*       out     = (float*)d_out;

    cudaFuncSetAttribute(k_all, cudaFuncAttributeMaxDynamicSharedMemorySize, SC_SMEM);
    k_all<<<SC_GRID, SC_THREADS, SC_SMEM>>>(feature, W1, b1, W2, b2, W3, b3,
                                            W4, b4, tr, te, out);
}